// round 9
// baseline (speedup 1.0000x reference)
#include <cuda_runtime.h>
#include <cstdint>

// ---------------------------------------------------------------------------
// Problem constants
// ---------------------------------------------------------------------------
constexpr int kNQ  = 1000;
constexpr int kBS  = 4;
constexpr int kC   = 256;
constexpr int kNH  = 8;
constexpr int kHD  = 32;
constexpr int kFFN = 512;
constexpr int kM   = kBS * kNQ;    // 4000
constexpr float kEPS   = 1e-5f;
constexpr float kScale = 0.17677669529663687f;  // 1/sqrt(HD)

// ---------------------------------------------------------------------------
// Scratch (static device globals)
// ---------------------------------------------------------------------------
__device__ float g_x0  [kM * kC];
__device__ float g_xq  [kM * kC];
__device__ float g_qk  [kM * 512];          // merged Q|K projections
__device__ float g_v   [kM * kC];
__device__ float g_attn[kM * kC];
__device__ float g_tmp [kM * kFFN];
__device__ float g_x1  [kM * kC];
__device__ float g_x2  [kM * kC];
__device__ float g_ms  [kM * kC];
__device__ float g_offaw[kM * 96];          // 64 offsets | 32 aw logits per row
__device__ float g_wcat[96 * kC];           // so_w | aw_w concatenated
__device__ float g_bcat[96];
__device__ float g_vpwt[kC * kC];           // vp_w transposed: Wt[c][o]

// ---------------------------------------------------------------------------
// helpers
// ---------------------------------------------------------------------------
__device__ __forceinline__ float tf32r(float x) {
    asm("cvt.rna.tf32.f32 %0, %0;" : "+f"(x));
    return x;
}
__device__ __forceinline__ uint32_t tf32u(float x) {
    asm("cvt.rna.tf32.f32 %0, %0;" : "+f"(x));
    return __float_as_uint(x);
}

__device__ __forceinline__ void mma_tf32(float* c, const uint32_t* a,
                                         const uint32_t* b) {
    asm volatile(
        "mma.sync.aligned.m16n8k8.row.col.f32.tf32.tf32.f32 "
        "{%0,%1,%2,%3}, {%4,%5,%6,%7}, {%8,%9}, {%0,%1,%2,%3};"
        : "+f"(c[0]), "+f"(c[1]), "+f"(c[2]), "+f"(c[3])
        : "r"(a[0]), "r"(a[1]), "r"(a[2]), "r"(a[3]),
          "r"(b[0]), "r"(b[1]));
}

__device__ __forceinline__ void cp_async16(uint32_t saddr, const void* g) {
    asm volatile("cp.async.ca.shared.global [%0], [%1], 16;"
                 :: "r"(saddr), "l"(g));
}
__device__ __forceinline__ void cp_commit() {
    asm volatile("cp.async.commit_group;");
}
__device__ __forceinline__ void cp_wait0() {
    asm volatile("cp.async.wait_group 0;");
}

// ---------------------------------------------------------------------------
// prep: (a) transpose query/query_pos into x0 / x0+pos,
//       (b) transpose vp_w -> g_vpwt, (c) concat so_w|aw_w -> g_wcat/g_bcat
// ---------------------------------------------------------------------------
constexpr int kPrepA = kM * kC;
constexpr int kPrepB = kPrepA + kC * kC;
constexpr int kPrepC = kPrepB + 64 * kC;
constexpr int kPrepD = kPrepC + 32 * kC;
constexpr int kPrepE = kPrepD + 96;

__global__ void prep_kernel(const float* __restrict__ query,
                            const float* __restrict__ qpos,
                            const float* __restrict__ vp_w,
                            const float* __restrict__ so_w,
                            const float* __restrict__ aw_w,
                            const float* __restrict__ so_b,
                            const float* __restrict__ aw_b)
{
    int i = blockIdx.x * blockDim.x + threadIdx.x;
    if (i < kPrepA) {
        int c = i & (kC - 1);
        int r = i >> 8;
        int b = r / kNQ;
        int q = r - b * kNQ;
        int src = (q * kBS + b) * kC + c;
        float xv = query[src];
        g_x0[i] = xv;
        g_xq[i] = xv + qpos[src];
    } else if (i < kPrepB) {
        int j = i - kPrepA;
        int o = j >> 8, c = j & 255;
        g_vpwt[c * kC + o] = vp_w[j];
    } else if (i < kPrepC) {
        int j = i - kPrepB;
        g_wcat[j] = so_w[j];
    } else if (i < kPrepD) {
        int j = i - kPrepC;
        g_wcat[64 * kC + j] = aw_w[j];
    } else if (i < kPrepE) {
        int j = i - kPrepD;
        g_bcat[j] = (j < 64) ? so_b[j] : aw_b[j - 64];
    }
}

// ---------------------------------------------------------------------------
// cp.async-pipelined TF32 GEMM:  C[M,N] = A[M,K] @ W[N,K]^T + bias (opt ReLU)
// ---------------------------------------------------------------------------
__global__ __launch_bounds__(128)
void mma_gemm(const float* __restrict__ A, const float* __restrict__ W,
              const float* __restrict__ bias, float* __restrict__ Co,
              int M, int N, int K, int relu)
{
    constexpr int LD = 36;
    __shared__ float sA[2][64][LD];
    __shared__ float sB[2][64][LD];
    constexpr uint32_t kStageA = 64 * LD * 4;

    int t    = threadIdx.x;
    int warp = t >> 5, lane = t & 31;
    int wm0  = (warp >> 1) << 5;
    int wn0  = (warp & 1) << 5;
    int qr   = lane >> 2;
    int qc   = lane & 3;
    int m0   = blockIdx.y * 64;
    int n0   = blockIdx.x * 64;

    const float* Ap[4]; const float* Bp[4];
    uint32_t sAo[4], sBo[4];
#pragma unroll
    for (int ld = 0; ld < 4; ld++) {
        int f   = t + (ld << 7);
        int row = f >> 3;
        int col = (f & 7) << 2;
        int m = m0 + row; if (m > M - 1) m = M - 1;
        int n = n0 + row; if (n > N - 1) n = N - 1;
        Ap[ld] = A + (size_t)m * K + col;
        Bp[ld] = W + (size_t)n * K + col;
        sAo[ld] = (uint32_t)__cvta_generic_to_shared(&sA[0][row][col]);
        sBo[ld] = (uint32_t)__cvta_generic_to_shared(&sB[0][row][col]);
    }

    float c[2][4][4] = {};

#pragma unroll
    for (int ld = 0; ld < 4; ld++) {
        cp_async16(sAo[ld], Ap[ld]);
        cp_async16(sBo[ld], Bp[ld]);
    }
    cp_commit();

    int KT = K >> 5;
    for (int kt = 0; kt < KT; kt++) {
        int cur = kt & 1;
        cp_wait0();
        __syncthreads();
        if (kt + 1 < KT) {
            int ko = (kt + 1) << 5;
            uint32_t so = (uint32_t)(cur ^ 1) * kStageA;
#pragma unroll
            for (int ld = 0; ld < 4; ld++) {
                cp_async16(sAo[ld] + so, Ap[ld] + ko);
                cp_async16(sBo[ld] + so, Bp[ld] + ko);
            }
            cp_commit();
        }
#pragma unroll
        for (int k8 = 0; k8 < 32; k8 += 8) {
            uint32_t a[2][4], b[4][2];
#pragma unroll
            for (int i = 0; i < 2; i++) {
                int r = wm0 + (i << 4) + qr;
                a[i][0] = tf32u(sA[cur][r    ][k8 + qc]);
                a[i][1] = tf32u(sA[cur][r + 8][k8 + qc]);
                a[i][2] = tf32u(sA[cur][r    ][k8 + qc + 4]);
                a[i][3] = tf32u(sA[cur][r + 8][k8 + qc + 4]);
            }
#pragma unroll
            for (int j = 0; j < 4; j++) {
                int r = wn0 + (j << 3) + qr;
                b[j][0] = tf32u(sB[cur][r][k8 + qc]);
                b[j][1] = tf32u(sB[cur][r][k8 + qc + 4]);
            }
#pragma unroll
            for (int i = 0; i < 2; i++)
#pragma unroll
                for (int j = 0; j < 4; j++)
                    mma_tf32(c[i][j], a[i], b[j]);
        }
        __syncthreads();
    }

#pragma unroll
    for (int j = 0; j < 4; j++) {
        int n = n0 + wn0 + (j << 3) + (qc << 1);
        if (n >= N) continue;
        float2 bz = *reinterpret_cast<const float2*>(bias + n);
#pragma unroll
        for (int i = 0; i < 2; i++) {
            int m = m0 + wm0 + (i << 4) + qr;
            if (m < M) {
                float2 o = make_float2(c[i][j][0] + bz.x, c[i][j][1] + bz.y);
                if (relu) { o.x = fmaxf(o.x, 0.f); o.y = fmaxf(o.y, 0.f); }
                *reinterpret_cast<float2*>(Co + (size_t)m * N + n) = o;
            }
            if (m + 8 < M) {
                float2 o = make_float2(c[i][j][2] + bz.x, c[i][j][3] + bz.y);
                if (relu) { o.x = fmaxf(o.x, 0.f); o.y = fmaxf(o.y, 0.f); }
                *reinterpret_cast<float2*>(Co + (size_t)(m + 8) * N + n) = o;
            }
        }
    }
}

// ---------------------------------------------------------------------------
// Tensor-core flash attention, cp.async double-buffered K/V.
// Raw fp32 K/V staged via LDGSTS; tf32 hi/lo split happens at fragment read.
// One __syncthreads per key tile.
// ---------------------------------------------------------------------------
__global__ __launch_bounds__(256)
void flash_mma_kernel(const float* __restrict__ QK, const float* __restrict__ V,
                      float* __restrict__ O)
{
    __shared__ float sK[2][32][36];   // raw K tiles
    __shared__ float sV[2][32][40];   // raw V tiles
    __shared__ float sP[128][36];     // Q staging, then per-warp P tiles
    constexpr uint32_t kStK = 32 * 36 * 4;
    constexpr uint32_t kStV = 32 * 40 * 4;

    int b    = blockIdx.y >> 3;
    int h    = blockIdx.y & 7;
    int q0   = blockIdx.x << 7;
    int t    = threadIdx.x;
    int warp = t >> 5, lane = t & 31;
    int lr   = lane >> 2;
    int lc   = lane & 3;

    // staging coords: 256 threads, one float4 each for K and V per tile
    int srow = t >> 3;
    int scol = (t & 7) << 2;
    uint32_t sKo = (uint32_t)__cvta_generic_to_shared(&sK[0][srow][scol]);
    uint32_t sVo = (uint32_t)__cvta_generic_to_shared(&sV[0][srow][scol]);
    const float* Kg = QK + 256 + h * kHD + scol;   // + row*512
    const float* Vg = V  +       h * kHD + scol;   // + row*256

    // prologue: tile 0 DMA (overlaps Q staging below)
    {
        int key = srow; if (key > kNQ - 1) key = kNQ - 1;
        cp_async16(sKo, Kg + (size_t)(b * kNQ + key) * 512);
        cp_async16(sVo, Vg + (size_t)(b * kNQ + key) * 256);
        cp_commit();
    }

    // stage Q (pre-scaled) into sP
#pragma unroll
    for (int i = 0; i < 4; i++) {
        int f   = t + (i << 8);
        int row = f >> 3;
        int col = (f & 7) << 2;
        int q   = q0 + row; if (q > kNQ - 1) q = kNQ - 1;
        float4 v4 = *reinterpret_cast<const float4*>(
            QK + (size_t)(b * kNQ + q) * 512 + h * kHD + col);
        sP[row][col + 0] = v4.x * kScale;
        sP[row][col + 1] = v4.y * kScale;
        sP[row][col + 2] = v4.z * kScale;
        sP[row][col + 3] = v4.w * kScale;
    }
    __syncthreads();

    // Q fragments (hi/lo split), warp-private rows
    int r0 = (warp << 4) + lr;
    int r1 = r0 + 8;
    uint32_t qh[4][4], ql[4][4];
#pragma unroll
    for (int ks = 0; ks < 4; ks++) {
        int c0 = (ks << 3) + lc, c1 = c0 + 4;
        float v0 = sP[r0][c0], v1 = sP[r1][c0];
        float v2 = sP[r0][c1], v3 = sP[r1][c1];
        float h0 = tf32r(v0), h1 = tf32r(v1), h2 = tf32r(v2), h3 = tf32r(v3);
        qh[ks][0] = __float_as_uint(h0);
        qh[ks][1] = __float_as_uint(h1);
        qh[ks][2] = __float_as_uint(h2);
        qh[ks][3] = __float_as_uint(h3);
        ql[ks][0] = __float_as_uint(tf32r(v0 - h0));
        ql[ks][1] = __float_as_uint(tf32r(v1 - h1));
        ql[ks][2] = __float_as_uint(tf32r(v2 - h2));
        ql[ks][3] = __float_as_uint(tf32r(v3 - h3));
    }

    float o[4][4] = {};
    float mrow0 = -1e30f, mrow1 = -1e30f;
    float lrow0 = 0.f,    lrow1 = 0.f;

    for (int kt = 0; kt < 32; kt++) {
        int k0  = kt << 5;
        int cur = kt & 1;
        cp_wait0();
        __syncthreads();       // staged tile visible; prior compute drained
        if (kt + 1 < 32) {
            int key = ((kt + 1) << 5) + srow; if (key > kNQ - 1) key = kNQ - 1;
            uint32_t so = (uint32_t)(cur ^ 1);
            cp_async16(sKo + so * kStK, Kg + (size_t)(b * kNQ + key) * 512);
            cp_async16(sVo + so * kStV, Vg + (size_t)(b * kNQ + key) * 256);
            cp_commit();
        }

        // ---- S = Q K^T  (tf32x3; K split at fragment read) ----
        float s[4][4];
#pragma unroll
        for (int nt = 0; nt < 4; nt++)
            s[nt][0] = s[nt][1] = s[nt][2] = s[nt][3] = 0.f;
#pragma unroll
        for (int ks = 0; ks < 4; ks++) {
#pragma unroll
            for (int nt = 0; nt < 4; nt++) {
                int kr = (nt << 3) + lr;
                int kc = (ks << 3) + lc;
                float rv0 = sK[cur][kr][kc];
                float rv1 = sK[cur][kr][kc + 4];
                float bh0 = tf32r(rv0), bh1 = tf32r(rv1);
                uint32_t bh[2] = { __float_as_uint(bh0), __float_as_uint(bh1) };
                uint32_t bl[2] = { __float_as_uint(tf32r(rv0 - bh0)),
                                   __float_as_uint(tf32r(rv1 - bh1)) };
                mma_tf32(s[nt], qh[ks], bh);
                mma_tf32(s[nt], qh[ks], bl);
                mma_tf32(s[nt], ql[ks], bh);
            }
        }

        // ---- mask invalid keys (last tile only) ----
        if (k0 + 32 > kNQ) {
#pragma unroll
            for (int nt = 0; nt < 4; nt++) {
                int col = k0 + (nt << 3) + (lc << 1);
                if (col     >= kNQ) { s[nt][0] = -1e30f; s[nt][2] = -1e30f; }
                if (col + 1 >= kNQ) { s[nt][1] = -1e30f; s[nt][3] = -1e30f; }
            }
        }

        // ---- online softmax (warp-local) ----
        float m0 = -1e30f, m1 = -1e30f;
#pragma unroll
        for (int nt = 0; nt < 4; nt++) {
            m0 = fmaxf(m0, fmaxf(s[nt][0], s[nt][1]));
            m1 = fmaxf(m1, fmaxf(s[nt][2], s[nt][3]));
        }
        m0 = fmaxf(m0, __shfl_xor_sync(0xffffffffu, m0, 1));
        m0 = fmaxf(m0, __shfl_xor_sync(0xffffffffu, m0, 2));
        m1 = fmaxf(m1, __shfl_xor_sync(0xffffffffu, m1, 1));
        m1 = fmaxf(m1, __shfl_xor_sync(0xffffffffu, m1, 2));
        float mn0 = fmaxf(mrow0, m0), mn1 = fmaxf(mrow1, m1);
        float al0 = __expf(mrow0 - mn0), al1 = __expf(mrow1 - mn1);
        float ls0 = 0.f, ls1 = 0.f;
#pragma unroll
        for (int nt = 0; nt < 4; nt++) {
            s[nt][0] = __expf(s[nt][0] - mn0); ls0 += s[nt][0];
            s[nt][1] = __expf(s[nt][1] - mn0); ls0 += s[nt][1];
            s[nt][2] = __expf(s[nt][2] - mn1); ls1 += s[nt][2];
            s[nt][3] = __expf(s[nt][3] - mn1); ls1 += s[nt][3];
        }
        ls0 += __shfl_xor_sync(0xffffffffu, ls0, 1);
        ls0 += __shfl_xor_sync(0xffffffffu, ls0, 2);
        ls1 += __shfl_xor_sync(0xffffffffu, ls1, 1);
        ls1 += __shfl_xor_sync(0xffffffffu, ls1, 2);
        lrow0 = lrow0 * al0 + ls0;
        lrow1 = lrow1 * al1 + ls1;
        mrow0 = mn0; mrow1 = mn1;
#pragma unroll
        for (int dt = 0; dt < 4; dt++) {
            o[dt][0] *= al0; o[dt][1] *= al0;
            o[dt][2] *= al1; o[dt][3] *= al1;
        }

        // ---- P -> warp-private smem (tf32-rounded) ----
#pragma unroll
        for (int nt = 0; nt < 4; nt++) {
            int pc = (nt << 3) + (lc << 1);
            sP[r0][pc]     = tf32r(s[nt][0]);
            sP[r0][pc + 1] = tf32r(s[nt][1]);
            sP[r1][pc]     = tf32r(s[nt][2]);
            sP[r1][pc + 1] = tf32r(s[nt][3]);
        }
        __syncwarp();

        // ---- O += P V  (V converted at fragment read) ----
#pragma unroll
        for (int ks2 = 0; ks2 < 4; ks2++) {
            int pc = (ks2 << 3) + lc;
            uint32_t a[4];
            a[0] = __float_as_uint(sP[r0][pc]);
            a[1] = __float_as_uint(sP[r1][pc]);
            a[2] = __float_as_uint(sP[r0][pc + 4]);
            a[3] = __float_as_uint(sP[r1][pc + 4]);
#pragma unroll
            for (int dt = 0; dt < 4; dt++) {
                uint32_t bb[2];
                bb[0] = tf32u(sV[cur][(ks2 << 3) + lc    ][(dt << 3) + lr]);
                bb[1] = tf32u(sV[cur][(ks2 << 3) + lc + 4][(dt << 3) + lr]);
                mma_tf32(o[dt], a, bb);
            }
        }
        __syncwarp();
    }

    // ---- normalize + store ----
    float inv0 = 1.f / lrow0, inv1 = 1.f / lrow1;
    int qa  = q0 + r0;
    int qb2 = q0 + r1;
#pragma unroll
    for (int dt = 0; dt < 4; dt++) {
        int col = h * kHD + (dt << 3) + (lc << 1);
        if (qa < kNQ) {
            float2 ov = make_float2(o[dt][0] * inv0, o[dt][1] * inv0);
            *reinterpret_cast<float2*>(O + (size_t)(b * kNQ + qa) * kC + col) = ov;
        }
        if (qb2 < kNQ) {
            float2 ov = make_float2(o[dt][2] * inv1, o[dt][3] * inv1);
            *reinterpret_cast<float2*>(O + (size_t)(b * kNQ + qb2) * kC + col) = ov;
        }
    }
}

// ---------------------------------------------------------------------------
// Residual + LayerNorm; optional fused xq = LN(out) + qpos
// ---------------------------------------------------------------------------
__global__ __launch_bounds__(256)
void ln_kernel(const float* __restrict__ X, const float* __restrict__ Y,
               const float* __restrict__ gam, const float* __restrict__ bet,
               float* __restrict__ out, int transpose_out,
               const float* __restrict__ qpos, float* __restrict__ xq_out)
{
    int r = blockIdx.x, t = threadIdx.x;
    float v = X[(size_t)r * kC + t] + Y[(size_t)r * kC + t];
    float s1 = v, s2 = v * v;
#pragma unroll
    for (int off = 16; off; off >>= 1) {
        s1 += __shfl_xor_sync(0xffffffffu, s1, off);
        s2 += __shfl_xor_sync(0xffffffffu, s2, off);
    }
    __shared__ float r1[8], r2[8];
    int w = t >> 5, lane = t & 31;
    if (lane == 0) { r1[w] = s1; r2[w] = s2; }
    __syncthreads();
    if (w == 0) {
        float a  = (lane < 8) ? r1[lane] : 0.f;
        float bq = (lane < 8) ? r2[lane] : 0.f;
#pragma unroll
        for (int off = 4; off; off >>= 1) {
            a  += __shfl_xor_sync(0xffffffffu, a, off);
            bq += __shfl_xor_sync(0xffffffffu, bq, off);
        }
        if (lane == 0) { r1[0] = a; r2[0] = bq; }
    }
    __syncthreads();
    float mean = r1[0] * (1.f / kC);
    float var  = r2[0] * (1.f / kC) - mean * mean;
    float rstd = rsqrtf(var + kEPS);
    float oo = (v - mean) * rstd * gam[t] + bet[t];
    int b = r / kNQ, q = r - b * kNQ;
    size_t oi = transpose_out ? (size_t)(q * kBS + b) * kC + t
                              : (size_t)r * kC + t;
    out[oi] = oo;
    if (xq_out)
        xq_out[(size_t)r * kC + t] = oo + qpos[(q * kBS + b) * kC + t];
}

// ---------------------------------------------------------------------------
// Fused deformable sampling + value projection (+ inline P=4 softmax).
// ---------------------------------------------------------------------------
__global__ __launch_bounds__(256)
void msfused_kernel(const float* __restrict__ value,
                    const float* __restrict__ refp,
                    const float* __restrict__ vp_b)
{
    __shared__ float sAcc[kNH][kC + 4];

    int rq   = blockIdx.x;
    int b    = rq / kNQ;
    int t    = threadIdx.x;
    int warp = t >> 5, lane = t & 31;
    int h    = warp;

    float rx = refp[rq * 2 + 0];
    float ry = refp[rq * 2 + 1];

    const float* pl = g_offaw + rq * 96 + 64 + h * 4;
    float l0 = pl[0], l1 = pl[1], l2 = pl[2], l3 = pl[3];
    float mx = fmaxf(fmaxf(l0, l1), fmaxf(l2, l3));
    float e0 = __expf(l0 - mx), e1 = __expf(l1 - mx);
    float e2 = __expf(l2 - mx), e3 = __expf(l3 - mx);
    float einv = 1.f / (e0 + e1 + e2 + e3);
    float awv[4] = {e0 * einv, e1 * einv, e2 * einv, e3 * einv};

    const float4 z4 = make_float4(0.f, 0.f, 0.f, 0.f);
    float4 a0 = z4, a1 = z4;
    float wsum = 0.f;

#pragma unroll
    for (int p = 0; p < 4; p++) {
        float ox = g_offaw[rq * 96 + h * 8 + p * 2 + 0];
        float oy = g_offaw[rq * 96 + h * 8 + p * 2 + 1];
        float wa = awv[p];
        float lx = rx + ox / 100.f;
        float ly = ry + oy / 200.f;
        float xim = lx * 100.f - 0.5f;
        float yim = ly * 200.f - 0.5f;
        float xf = floorf(xim), yf = floorf(yim);
        float fx = xim - xf, fy = yim - yf;
        int x0 = (int)xf, y0 = (int)yf;
#pragma unroll
        for (int dy = 0; dy < 2; dy++) {
#pragma unroll
            for (int dx = 0; dx < 2; dx++) {
                int xi = x0 + dx, yi = y0 + dy;
                if (xi >= 0 && xi < 100 && yi >= 0 && yi < 200) {
                    float w = wa * (dx ? fx : 1.f - fx) * (dy ? fy : 1.f - fy);
                    const float4* row = reinterpret_cast<const float4*>(
                        value + (size_t)((yi * 100 + xi) * kBS + b) * kC
                              + (lane << 3));
                    float4 v0 = row[0], v1 = row[1];
                    a0.x = fmaf(w, v0.x, a0.x); a0.y = fmaf(w, v0.y, a0.y);
                    a0.z = fmaf(w, v0.z, a0.z); a0.w = fmaf(w, v0.w, a0.w);
                    a1.x = fmaf(w, v1.x, a1.x); a1.y = fmaf(w, v1.y, a1.y);
                    a1.z = fmaf(w, v1.z, a1.z); a1.w = fmaf(w, v1.w, a1.w);
                    wsum += w;
                }
            }
        }
    }

    *reinterpret_cast<float4*>(&sAcc[h][(lane << 3)])     = a0;
    *reinterpret_cast<float4*>(&sAcc[h][(lane << 3) + 4]) = a1;
    __syncwarp();

    int oc = h * kHD + lane;
    float acc = wsum * vp_b[oc];
    const float* wt = g_vpwt + oc;
#pragma unroll 8
    for (int c2 = 0; c2 < kC; c2++)
        acc = fmaf(sAcc[h][c2], wt[(size_t)c2 * kC], acc);

    g_ms[(size_t)rq * kC + oc] = acc;
}

// ---------------------------------------------------------------------------
// Launch sequence
// ---------------------------------------------------------------------------
extern "C" void kernel_launch(void* const* d_in, const int* in_sizes, int n_in,
                              void* d_out, int out_size)
{
    const float* query = (const float*)d_in[0];
    const float* value = (const float*)d_in[1];
    const float* qpos  = (const float*)d_in[2];
    const float* refp  = (const float*)d_in[3];
    const float* in_w  = (const float*)d_in[6];
    const float* in_b  = (const float*)d_in[7];
    const float* mha_ow= (const float*)d_in[8];
    const float* mha_ob= (const float*)d_in[9];
    const float* so_w  = (const float*)d_in[10];
    const float* so_b  = (const float*)d_in[11];
    const float* aw_w  = (const float*)d_in[12];
    const float* aw_b  = (const float*)d_in[13];
    const float* vp_w  = (const float*)d_in[14];
    const float* vp_b  = (const float*)d_in[15];
    const float* op_w  = (const float*)d_in[16];
    const float* op_b  = (const float*)d_in[17];
    const float* f_w1  = (const float*)d_in[18];
    const float* f_b1  = (const float*)d_in[19];
    const float* f_w2  = (const float*)d_in[20];
    const float* f_b2  = (const float*)d_in[21];
    const float* ln1g  = (const float*)d_in[22];
    const float* ln1b  = (const float*)d_in[23];
    const float* ln2g  = (const float*)d_in[24];
    const float* ln2b  = (const float*)d_in[25];
    const float* ln3g  = (const float*)d_in[26];
    const float* ln3b  = (const float*)d_in[27];
    float* out = (float*)d_out;

    float *x0, *xq, *qk, *vb, *attn, *tmp, *x1, *x2, *offaw, *ms, *wcat, *bcat;
    cudaGetSymbolAddress((void**)&x0,    g_x0);
    cudaGetSymbolAddress((void**)&xq,    g_xq);
    cudaGetSymbolAddress((void**)&qk,    g_qk);
    cudaGetSymbolAddress((void**)&vb,    g_v);
    cudaGetSymbolAddress((void**)&attn,  g_attn);
    cudaGetSymbolAddress((void**)&tmp,   g_tmp);
    cudaGetSymbolAddress((void**)&x1,    g_x1);
    cudaGetSymbolAddress((void**)&x2,    g_x2);
    cudaGetSymbolAddress((void**)&offaw, g_offaw);
    cudaGetSymbolAddress((void**)&ms,    g_ms);
    cudaGetSymbolAddress((void**)&wcat,  g_wcat);
    cudaGetSymbolAddress((void**)&bcat,  g_bcat);

    // 1) prep
    prep_kernel<<<(kPrepE + 255) / 256, 256>>>(query, qpos, vp_w,
                                               so_w, aw_w, so_b, aw_b);

    // 2) merged Q|K projection (N=512) and V projection
    mma_gemm<<<dim3(8, 63), 128>>>(xq, in_w,             in_b,       qk, kM, 512, kC, 0);
    mma_gemm<<<dim3(4, 63), 128>>>(x0, in_w + 512 * 256, in_b + 512, vb, kM, kC,  kC, 0);

    // 3) tensor-core flash attention (cp.async double-buffered)
    flash_mma_kernel<<<dim3(8, kBS * kNH), 256>>>(qk, vb, attn);

    // 4) out-proj + residual + LN1 (fused: xq = x1 + qpos)
    mma_gemm<<<dim3(4, 63), 128>>>(attn, mha_ow, mha_ob, tmp, kM, kC, kC, 0);
    ln_kernel<<<kM, 256>>>(x0, tmp, ln1g, ln1b, x1, 0, qpos, xq);

    // 5) merged offset+weight projection (N=96)
    mma_gemm<<<dim3(2, 63), 128>>>(xq, wcat, bcat, offaw, kM, 96, kC, 0);

    // 6) fused raw-value sampling + per-head projection (+inline softmax)
    msfused_kernel<<<kM, 256>>>(value, refp, vp_b);

    // 7) msdeform out-proj + residual + LN2
    mma_gemm<<<dim3(4, 63), 128>>>(ms, op_w, op_b, tmp, kM, kC, kC, 0);
    ln_kernel<<<kM, 256>>>(x1, tmp, ln2g, ln2b, x2, 0, nullptr, nullptr);

    // 8) FFN + residual + LN3 (LN3 writes transposed into d_out)
    mma_gemm<<<dim3(8, 63), 128>>>(x2,  f_w1, f_b1, tmp, kM, kFFN, kC,   1);
    mma_gemm<<<dim3(4, 63), 128>>>(tmp, f_w2, f_b2, x0,  kM, kC,   kFFN, 0);
    ln_kernel<<<kM, 256>>>(x2, x0, ln3g, ln3b, out, 1, nullptr, nullptr);
}

// round 10
// speedup vs baseline: 1.0156x; 1.0156x over previous
#include <cuda_runtime.h>
#include <cstdint>

// ---------------------------------------------------------------------------
// Problem constants
// ---------------------------------------------------------------------------
constexpr int kNQ  = 1000;
constexpr int kBS  = 4;
constexpr int kC   = 256;
constexpr int kNH  = 8;
constexpr int kHD  = 32;
constexpr int kFFN = 512;
constexpr int kM   = kBS * kNQ;    // 4000
constexpr float kEPS   = 1e-5f;
constexpr float kScale = 0.17677669529663687f;  // 1/sqrt(HD)

// ---------------------------------------------------------------------------
// Scratch (static device globals)
// ---------------------------------------------------------------------------
__device__ float g_x0  [kM * kC];
__device__ float g_xq  [kM * kC];
__device__ float g_qk  [kM * 512];          // merged Q|K projections
__device__ float g_v   [kM * kC];
__device__ float g_attn[kM * kC];
__device__ float g_tmp [kM * kFFN];
__device__ float g_x1  [kM * kC];
__device__ float g_x2  [kM * kC];
__device__ float g_ms  [kM * kC];
__device__ float g_offaw[kM * 96];          // 64 offsets | 32 aw logits per row
__device__ float g_wcat[96 * kC];           // so_w | aw_w concatenated
__device__ float g_bcat[96];
__device__ float g_vpwt[kC * kC];           // vp_w transposed: Wt[c][o]

// ---------------------------------------------------------------------------
// helpers
// ---------------------------------------------------------------------------
__device__ __forceinline__ float tf32r(float x) {
    asm("cvt.rna.tf32.f32 %0, %0;" : "+f"(x));
    return x;
}
__device__ __forceinline__ uint32_t tf32u(float x) {
    asm("cvt.rna.tf32.f32 %0, %0;" : "+f"(x));
    return __float_as_uint(x);
}

__device__ __forceinline__ void mma_tf32(float* c, const uint32_t* a,
                                         const uint32_t* b) {
    asm volatile(
        "mma.sync.aligned.m16n8k8.row.col.f32.tf32.tf32.f32 "
        "{%0,%1,%2,%3}, {%4,%5,%6,%7}, {%8,%9}, {%0,%1,%2,%3};"
        : "+f"(c[0]), "+f"(c[1]), "+f"(c[2]), "+f"(c[3])
        : "r"(a[0]), "r"(a[1]), "r"(a[2]), "r"(a[3]),
          "r"(b[0]), "r"(b[1]));
}

__device__ __forceinline__ void cp_async16(uint32_t saddr, const void* g) {
    asm volatile("cp.async.ca.shared.global [%0], [%1], 16;"
                 :: "r"(saddr), "l"(g));
}
__device__ __forceinline__ void cp_commit() {
    asm volatile("cp.async.commit_group;");
}
__device__ __forceinline__ void cp_wait0() {
    asm volatile("cp.async.wait_group 0;");
}

// ---------------------------------------------------------------------------
// prep: (a) transpose query/query_pos into x0 / x0+pos,
//       (b) transpose vp_w -> g_vpwt, (c) concat so_w|aw_w -> g_wcat/g_bcat
// ---------------------------------------------------------------------------
constexpr int kPrepA = kM * kC;
constexpr int kPrepB = kPrepA + kC * kC;
constexpr int kPrepC = kPrepB + 64 * kC;
constexpr int kPrepD = kPrepC + 32 * kC;
constexpr int kPrepE = kPrepD + 96;

__global__ void prep_kernel(const float* __restrict__ query,
                            const float* __restrict__ qpos,
                            const float* __restrict__ vp_w,
                            const float* __restrict__ so_w,
                            const float* __restrict__ aw_w,
                            const float* __restrict__ so_b,
                            const float* __restrict__ aw_b)
{
    int i = blockIdx.x * blockDim.x + threadIdx.x;
    if (i < kPrepA) {
        int c = i & (kC - 1);
        int r = i >> 8;
        int b = r / kNQ;
        int q = r - b * kNQ;
        int src = (q * kBS + b) * kC + c;
        float xv = query[src];
        g_x0[i] = xv;
        g_xq[i] = xv + qpos[src];
    } else if (i < kPrepB) {
        int j = i - kPrepA;
        int o = j >> 8, c = j & 255;
        g_vpwt[c * kC + o] = vp_w[j];
    } else if (i < kPrepC) {
        int j = i - kPrepB;
        g_wcat[j] = so_w[j];
    } else if (i < kPrepD) {
        int j = i - kPrepC;
        g_wcat[64 * kC + j] = aw_w[j];
    } else if (i < kPrepE) {
        int j = i - kPrepD;
        g_bcat[j] = (j < 64) ? so_b[j] : aw_b[j - 64];
    }
}

// ---------------------------------------------------------------------------
// cp.async-pipelined TF32 GEMM:  C[M,N] = A[M,K] @ W[N,K]^T + bias (opt ReLU)
// ---------------------------------------------------------------------------
__global__ __launch_bounds__(128)
void mma_gemm(const float* __restrict__ A, const float* __restrict__ W,
              const float* __restrict__ bias, float* __restrict__ Co,
              int M, int N, int K, int relu)
{
    constexpr int LD = 36;
    __shared__ float sA[2][64][LD];
    __shared__ float sB[2][64][LD];
    constexpr uint32_t kStageA = 64 * LD * 4;

    int t    = threadIdx.x;
    int warp = t >> 5, lane = t & 31;
    int wm0  = (warp >> 1) << 5;
    int wn0  = (warp & 1) << 5;
    int qr   = lane >> 2;
    int qc   = lane & 3;
    int m0   = blockIdx.y * 64;
    int n0   = blockIdx.x * 64;

    const float* Ap[4]; const float* Bp[4];
    uint32_t sAo[4], sBo[4];
#pragma unroll
    for (int ld = 0; ld < 4; ld++) {
        int f   = t + (ld << 7);
        int row = f >> 3;
        int col = (f & 7) << 2;
        int m = m0 + row; if (m > M - 1) m = M - 1;
        int n = n0 + row; if (n > N - 1) n = N - 1;
        Ap[ld] = A + (size_t)m * K + col;
        Bp[ld] = W + (size_t)n * K + col;
        sAo[ld] = (uint32_t)__cvta_generic_to_shared(&sA[0][row][col]);
        sBo[ld] = (uint32_t)__cvta_generic_to_shared(&sB[0][row][col]);
    }

    float c[2][4][4] = {};

#pragma unroll
    for (int ld = 0; ld < 4; ld++) {
        cp_async16(sAo[ld], Ap[ld]);
        cp_async16(sBo[ld], Bp[ld]);
    }
    cp_commit();

    int KT = K >> 5;
    for (int kt = 0; kt < KT; kt++) {
        int cur = kt & 1;
        cp_wait0();
        __syncthreads();
        if (kt + 1 < KT) {
            int ko = (kt + 1) << 5;
            uint32_t so = (uint32_t)(cur ^ 1) * kStageA;
#pragma unroll
            for (int ld = 0; ld < 4; ld++) {
                cp_async16(sAo[ld] + so, Ap[ld] + ko);
                cp_async16(sBo[ld] + so, Bp[ld] + ko);
            }
            cp_commit();
        }
#pragma unroll
        for (int k8 = 0; k8 < 32; k8 += 8) {
            uint32_t a[2][4], b[4][2];
#pragma unroll
            for (int i = 0; i < 2; i++) {
                int r = wm0 + (i << 4) + qr;
                a[i][0] = tf32u(sA[cur][r    ][k8 + qc]);
                a[i][1] = tf32u(sA[cur][r + 8][k8 + qc]);
                a[i][2] = tf32u(sA[cur][r    ][k8 + qc + 4]);
                a[i][3] = tf32u(sA[cur][r + 8][k8 + qc + 4]);
            }
#pragma unroll
            for (int j = 0; j < 4; j++) {
                int r = wn0 + (j << 3) + qr;
                b[j][0] = tf32u(sB[cur][r][k8 + qc]);
                b[j][1] = tf32u(sB[cur][r][k8 + qc + 4]);
            }
#pragma unroll
            for (int i = 0; i < 2; i++)
#pragma unroll
                for (int j = 0; j < 4; j++)
                    mma_tf32(c[i][j], a[i], b[j]);
        }
        __syncthreads();
    }

#pragma unroll
    for (int j = 0; j < 4; j++) {
        int n = n0 + wn0 + (j << 3) + (qc << 1);
        if (n >= N) continue;
        float2 bz = *reinterpret_cast<const float2*>(bias + n);
#pragma unroll
        for (int i = 0; i < 2; i++) {
            int m = m0 + wm0 + (i << 4) + qr;
            if (m < M) {
                float2 o = make_float2(c[i][j][0] + bz.x, c[i][j][1] + bz.y);
                if (relu) { o.x = fmaxf(o.x, 0.f); o.y = fmaxf(o.y, 0.f); }
                *reinterpret_cast<float2*>(Co + (size_t)m * N + n) = o;
            }
            if (m + 8 < M) {
                float2 o = make_float2(c[i][j][2] + bz.x, c[i][j][3] + bz.y);
                if (relu) { o.x = fmaxf(o.x, 0.f); o.y = fmaxf(o.y, 0.f); }
                *reinterpret_cast<float2*>(Co + (size_t)(m + 8) * N + n) = o;
            }
        }
    }
}

// ---------------------------------------------------------------------------
// Tensor-core flash attention: cp.async double-buffered raw K/V +
// cooperative staging-time K hi/lo split (cheap ALU, conflict-free frags).
// ---------------------------------------------------------------------------
__global__ __launch_bounds__(256)
void flash_mma_kernel(const float* __restrict__ QK, const float* __restrict__ V,
                      float* __restrict__ O)
{
    __shared__ float sKr[2][32][32];  // raw K (cp.async target), 8 KB
    __shared__ float sKh[32][36];     // K hi (tf32), conflict-free frags
    __shared__ float sKl[32][36];     // K lo
    __shared__ float sV [2][32][40];  // raw V, converted at fragment read
    __shared__ float sP [128][36];    // Q staging, then per-warp P tiles
    constexpr uint32_t kStK = 32 * 32 * 4;
    constexpr uint32_t kStV = 32 * 40 * 4;

    int b    = blockIdx.y >> 3;
    int h    = blockIdx.y & 7;
    int q0   = blockIdx.x << 7;
    int t    = threadIdx.x;
    int warp = t >> 5, lane = t & 31;
    int lr   = lane >> 2;
    int lc   = lane & 3;

    // staging coords: 256 threads, one float4 each for K and V per tile
    int srow = t >> 3;
    int scol = (t & 7) << 2;
    uint32_t sKo = (uint32_t)__cvta_generic_to_shared(&sKr[0][srow][scol]);
    uint32_t sVo = (uint32_t)__cvta_generic_to_shared(&sV[0][srow][scol]);
    const float* Kg = QK + 256 + h * kHD + scol;   // + row*512
    const float* Vg = V  +       h * kHD + scol;   // + row*256

    // prologue: tile 0 DMA (overlaps Q staging below)
    {
        int key = srow; if (key > kNQ - 1) key = kNQ - 1;
        cp_async16(sKo, Kg + (size_t)(b * kNQ + key) * 512);
        cp_async16(sVo, Vg + (size_t)(b * kNQ + key) * 256);
        cp_commit();
    }

    // stage Q (pre-scaled) into sP
#pragma unroll
    for (int i = 0; i < 4; i++) {
        int f   = t + (i << 8);
        int row = f >> 3;
        int col = (f & 7) << 2;
        int q   = q0 + row; if (q > kNQ - 1) q = kNQ - 1;
        float4 v4 = *reinterpret_cast<const float4*>(
            QK + (size_t)(b * kNQ + q) * 512 + h * kHD + col);
        sP[row][col + 0] = v4.x * kScale;
        sP[row][col + 1] = v4.y * kScale;
        sP[row][col + 2] = v4.z * kScale;
        sP[row][col + 3] = v4.w * kScale;
    }
    __syncthreads();

    // Q fragments (hi/lo split), warp-private rows
    int r0 = (warp << 4) + lr;
    int r1 = r0 + 8;
    uint32_t qh[4][4], ql[4][4];
#pragma unroll
    for (int ks = 0; ks < 4; ks++) {
        int c0 = (ks << 3) + lc, c1 = c0 + 4;
        float v0 = sP[r0][c0], v1 = sP[r1][c0];
        float v2 = sP[r0][c1], v3 = sP[r1][c1];
        float h0 = tf32r(v0), h1 = tf32r(v1), h2 = tf32r(v2), h3 = tf32r(v3);
        qh[ks][0] = __float_as_uint(h0);
        qh[ks][1] = __float_as_uint(h1);
        qh[ks][2] = __float_as_uint(h2);
        qh[ks][3] = __float_as_uint(h3);
        ql[ks][0] = __float_as_uint(tf32r(v0 - h0));
        ql[ks][1] = __float_as_uint(tf32r(v1 - h1));
        ql[ks][2] = __float_as_uint(tf32r(v2 - h2));
        ql[ks][3] = __float_as_uint(tf32r(v3 - h3));
    }

    float o[4][4] = {};
    float mrow0 = -1e30f, mrow1 = -1e30f;
    float lrow0 = 0.f,    lrow1 = 0.f;

    for (int kt = 0; kt < 32; kt++) {
        int k0  = kt << 5;
        int cur = kt & 1;
        cp_wait0();
        __syncthreads();   // raw tile visible; prev compute (sKh/sKl reads) done
        if (kt + 1 < 32) {
            int key = ((kt + 1) << 5) + srow; if (key > kNQ - 1) key = kNQ - 1;
            uint32_t so = (uint32_t)(cur ^ 1);
            cp_async16(sKo + so * kStK, Kg + (size_t)(b * kNQ + key) * 512);
            cp_async16(sVo + so * kStV, Vg + (size_t)(b * kNQ + key) * 256);
            cp_commit();
        }

        // ---- cooperative K split: raw -> tf32 hi/lo (one float4/thread) ----
        {
            float4 kv = *reinterpret_cast<const float4*>(&sKr[cur][srow][scol]);
            float h0 = tf32r(kv.x), h1 = tf32r(kv.y);
            float h2 = tf32r(kv.z), h3 = tf32r(kv.w);
            float4 hi = make_float4(h0, h1, h2, h3);
            float4 lo = make_float4(tf32r(kv.x - h0), tf32r(kv.y - h1),
                                    tf32r(kv.z - h2), tf32r(kv.w - h3));
            *reinterpret_cast<float4*>(&sKh[srow][scol]) = hi;
            *reinterpret_cast<float4*>(&sKl[srow][scol]) = lo;
        }
        __syncthreads();

        // ---- S = Q K^T  (tf32x3: qh*kh + qh*kl + ql*kh) ----
        float s[4][4];
#pragma unroll
        for (int nt = 0; nt < 4; nt++)
            s[nt][0] = s[nt][1] = s[nt][2] = s[nt][3] = 0.f;
#pragma unroll
        for (int ks = 0; ks < 4; ks++) {
#pragma unroll
            for (int nt = 0; nt < 4; nt++) {
                int kr = (nt << 3) + lr;
                int kc = (ks << 3) + lc;
                uint32_t bh[2], bl[2];
                bh[0] = __float_as_uint(sKh[kr][kc]);
                bh[1] = __float_as_uint(sKh[kr][kc + 4]);
                bl[0] = __float_as_uint(sKl[kr][kc]);
                bl[1] = __float_as_uint(sKl[kr][kc + 4]);
                mma_tf32(s[nt], qh[ks], bh);
                mma_tf32(s[nt], qh[ks], bl);
                mma_tf32(s[nt], ql[ks], bh);
            }
        }

        // ---- mask invalid keys (last tile only) ----
        if (k0 + 32 > kNQ) {
#pragma unroll
            for (int nt = 0; nt < 4; nt++) {
                int col = k0 + (nt << 3) + (lc << 1);
                if (col     >= kNQ) { s[nt][0] = -1e30f; s[nt][2] = -1e30f; }
                if (col + 1 >= kNQ) { s[nt][1] = -1e30f; s[nt][3] = -1e30f; }
            }
        }

        // ---- online softmax (warp-local) ----
        float m0 = -1e30f, m1 = -1e30f;
#pragma unroll
        for (int nt = 0; nt < 4; nt++) {
            m0 = fmaxf(m0, fmaxf(s[nt][0], s[nt][1]));
            m1 = fmaxf(m1, fmaxf(s[nt][2], s[nt][3]));
        }
        m0 = fmaxf(m0, __shfl_xor_sync(0xffffffffu, m0, 1));
        m0 = fmaxf(m0, __shfl_xor_sync(0xffffffffu, m0, 2));
        m1 = fmaxf(m1, __shfl_xor_sync(0xffffffffu, m1, 1));
        m1 = fmaxf(m1, __shfl_xor_sync(0xffffffffu, m1, 2));
        float mn0 = fmaxf(mrow0, m0), mn1 = fmaxf(mrow1, m1);
        float al0 = __expf(mrow0 - mn0), al1 = __expf(mrow1 - mn1);
        float ls0 = 0.f, ls1 = 0.f;
#pragma unroll
        for (int nt = 0; nt < 4; nt++) {
            s[nt][0] = __expf(s[nt][0] - mn0); ls0 += s[nt][0];
            s[nt][1] = __expf(s[nt][1] - mn0); ls0 += s[nt][1];
            s[nt][2] = __expf(s[nt][2] - mn1); ls1 += s[nt][2];
            s[nt][3] = __expf(s[nt][3] - mn1); ls1 += s[nt][3];
        }
        ls0 += __shfl_xor_sync(0xffffffffu, ls0, 1);
        ls0 += __shfl_xor_sync(0xffffffffu, ls0, 2);
        ls1 += __shfl_xor_sync(0xffffffffu, ls1, 1);
        ls1 += __shfl_xor_sync(0xffffffffu, ls1, 2);
        lrow0 = lrow0 * al0 + ls0;
        lrow1 = lrow1 * al1 + ls1;
        mrow0 = mn0; mrow1 = mn1;
#pragma unroll
        for (int dt = 0; dt < 4; dt++) {
            o[dt][0] *= al0; o[dt][1] *= al0;
            o[dt][2] *= al1; o[dt][3] *= al1;
        }

        // ---- P -> warp-private smem (tf32-rounded) ----
#pragma unroll
        for (int nt = 0; nt < 4; nt++) {
            int pc = (nt << 3) + (lc << 1);
            sP[r0][pc]     = tf32r(s[nt][0]);
            sP[r0][pc + 1] = tf32r(s[nt][1]);
            sP[r1][pc]     = tf32r(s[nt][2]);
            sP[r1][pc + 1] = tf32r(s[nt][3]);
        }
        __syncwarp();

        // ---- O += P V  (V converted at fragment read) ----
#pragma unroll
        for (int ks2 = 0; ks2 < 4; ks2++) {
            int pc = (ks2 << 3) + lc;
            uint32_t a[4];
            a[0] = __float_as_uint(sP[r0][pc]);
            a[1] = __float_as_uint(sP[r1][pc]);
            a[2] = __float_as_uint(sP[r0][pc + 4]);
            a[3] = __float_as_uint(sP[r1][pc + 4]);
#pragma unroll
            for (int dt = 0; dt < 4; dt++) {
                uint32_t bb[2];
                bb[0] = tf32u(sV[cur][(ks2 << 3) + lc    ][(dt << 3) + lr]);
                bb[1] = tf32u(sV[cur][(ks2 << 3) + lc + 4][(dt << 3) + lr]);
                mma_tf32(o[dt], a, bb);
            }
        }
        __syncwarp();
    }

    // ---- normalize + store ----
    float inv0 = 1.f / lrow0, inv1 = 1.f / lrow1;
    int qa  = q0 + r0;
    int qb2 = q0 + r1;
#pragma unroll
    for (int dt = 0; dt < 4; dt++) {
        int col = h * kHD + (dt << 3) + (lc << 1);
        if (qa < kNQ) {
            float2 ov = make_float2(o[dt][0] * inv0, o[dt][1] * inv0);
            *reinterpret_cast<float2*>(O + (size_t)(b * kNQ + qa) * kC + col) = ov;
        }
        if (qb2 < kNQ) {
            float2 ov = make_float2(o[dt][2] * inv1, o[dt][3] * inv1);
            *reinterpret_cast<float2*>(O + (size_t)(b * kNQ + qb2) * kC + col) = ov;
        }
    }
}

// ---------------------------------------------------------------------------
// Residual + LayerNorm; optional fused xq = LN(out) + qpos
// ---------------------------------------------------------------------------
__global__ __launch_bounds__(256)
void ln_kernel(const float* __restrict__ X, const float* __restrict__ Y,
               const float* __restrict__ gam, const float* __restrict__ bet,
               float* __restrict__ out, int transpose_out,
               const float* __restrict__ qpos, float* __restrict__ xq_out)
{
    int r = blockIdx.x, t = threadIdx.x;
    float v = X[(size_t)r * kC + t] + Y[(size_t)r * kC + t];
    float s1 = v, s2 = v * v;
#pragma unroll
    for (int off = 16; off; off >>= 1) {
        s1 += __shfl_xor_sync(0xffffffffu, s1, off);
        s2 += __shfl_xor_sync(0xffffffffu, s2, off);
    }
    __shared__ float r1[8], r2[8];
    int w = t >> 5, lane = t & 31;
    if (lane == 0) { r1[w] = s1; r2[w] = s2; }
    __syncthreads();
    if (w == 0) {
        float a  = (lane < 8) ? r1[lane] : 0.f;
        float bq = (lane < 8) ? r2[lane] : 0.f;
#pragma unroll
        for (int off = 4; off; off >>= 1) {
            a  += __shfl_xor_sync(0xffffffffu, a, off);
            bq += __shfl_xor_sync(0xffffffffu, bq, off);
        }
        if (lane == 0) { r1[0] = a; r2[0] = bq; }
    }
    __syncthreads();
    float mean = r1[0] * (1.f / kC);
    float var  = r2[0] * (1.f / kC) - mean * mean;
    float rstd = rsqrtf(var + kEPS);
    float oo = (v - mean) * rstd * gam[t] + bet[t];
    int b = r / kNQ, q = r - b * kNQ;
    size_t oi = transpose_out ? (size_t)(q * kBS + b) * kC + t
                              : (size_t)r * kC + t;
    out[oi] = oo;
    if (xq_out)
        xq_out[(size_t)r * kC + t] = oo + qpos[(q * kBS + b) * kC + t];
}

// ---------------------------------------------------------------------------
// Fused deformable sampling + value projection (+ inline P=4 softmax).
// ---------------------------------------------------------------------------
__global__ __launch_bounds__(256)
void msfused_kernel(const float* __restrict__ value,
                    const float* __restrict__ refp,
                    const float* __restrict__ vp_b)
{
    __shared__ float sAcc[kNH][kC + 4];

    int rq   = blockIdx.x;
    int b    = rq / kNQ;
    int t    = threadIdx.x;
    int warp = t >> 5, lane = t & 31;
    int h    = warp;

    float rx = refp[rq * 2 + 0];
    float ry = refp[rq * 2 + 1];

    const float* pl = g_offaw + rq * 96 + 64 + h * 4;
    float l0 = pl[0], l1 = pl[1], l2 = pl[2], l3 = pl[3];
    float mx = fmaxf(fmaxf(l0, l1), fmaxf(l2, l3));
    float e0 = __expf(l0 - mx), e1 = __expf(l1 - mx);
    float e2 = __expf(l2 - mx), e3 = __expf(l3 - mx);
    float einv = 1.f / (e0 + e1 + e2 + e3);
    float awv[4] = {e0 * einv, e1 * einv, e2 * einv, e3 * einv};

    const float4 z4 = make_float4(0.f, 0.f, 0.f, 0.f);
    float4 a0 = z4, a1 = z4;
    float wsum = 0.f;

#pragma unroll
    for (int p = 0; p < 4; p++) {
        float ox = g_offaw[rq * 96 + h * 8 + p * 2 + 0];
        float oy = g_offaw[rq * 96 + h * 8 + p * 2 + 1];
        float wa = awv[p];
        float lx = rx + ox / 100.f;
        float ly = ry + oy / 200.f;
        float xim = lx * 100.f - 0.5f;
        float yim = ly * 200.f - 0.5f;
        float xf = floorf(xim), yf = floorf(yim);
        float fx = xim - xf, fy = yim - yf;
        int x0 = (int)xf, y0 = (int)yf;
#pragma unroll
        for (int dy = 0; dy < 2; dy++) {
#pragma unroll
            for (int dx = 0; dx < 2; dx++) {
                int xi = x0 + dx, yi = y0 + dy;
                if (xi >= 0 && xi < 100 && yi >= 0 && yi < 200) {
                    float w = wa * (dx ? fx : 1.f - fx) * (dy ? fy : 1.f - fy);
                    const float4* row = reinterpret_cast<const float4*>(
                        value + (size_t)((yi * 100 + xi) * kBS + b) * kC
                              + (lane << 3));
                    float4 v0 = row[0], v1 = row[1];
                    a0.x = fmaf(w, v0.x, a0.x); a0.y = fmaf(w, v0.y, a0.y);
                    a0.z = fmaf(w, v0.z, a0.z); a0.w = fmaf(w, v0.w, a0.w);
                    a1.x = fmaf(w, v1.x, a1.x); a1.y = fmaf(w, v1.y, a1.y);
                    a1.z = fmaf(w, v1.z, a1.z); a1.w = fmaf(w, v1.w, a1.w);
                    wsum += w;
                }
            }
        }
    }

    *reinterpret_cast<float4*>(&sAcc[h][(lane << 3)])     = a0;
    *reinterpret_cast<float4*>(&sAcc[h][(lane << 3) + 4]) = a1;
    __syncwarp();

    int oc = h * kHD + lane;
    float acc = wsum * vp_b[oc];
    const float* wt = g_vpwt + oc;
#pragma unroll 8
    for (int c2 = 0; c2 < kC; c2++)
        acc = fmaf(sAcc[h][c2], wt[(size_t)c2 * kC], acc);

    g_ms[(size_t)rq * kC + oc] = acc;
}

// ---------------------------------------------------------------------------
// Launch sequence
// ---------------------------------------------------------------------------
extern "C" void kernel_launch(void* const* d_in, const int* in_sizes, int n_in,
                              void* d_out, int out_size)
{
    const float* query = (const float*)d_in[0];
    const float* value = (const float*)d_in[1];
    const float* qpos  = (const float*)d_in[2];
    const float* refp  = (const float*)d_in[3];
    const float* in_w  = (const float*)d_in[6];
    const float* in_b  = (const float*)d_in[7];
    const float* mha_ow= (const float*)d_in[8];
    const float* mha_ob= (const float*)d_in[9];
    const float* so_w  = (const float*)d_in[10];
    const float* so_b  = (const float*)d_in[11];
    const float* aw_w  = (const float*)d_in[12];
    const float* aw_b  = (const float*)d_in[13];
    const float* vp_w  = (const float*)d_in[14];
    const float* vp_b  = (const float*)d_in[15];
    const float* op_w  = (const float*)d_in[16];
    const float* op_b  = (const float*)d_in[17];
    const float* f_w1  = (const float*)d_in[18];
    const float* f_b1  = (const float*)d_in[19];
    const float* f_w2  = (const float*)d_in[20];
    const float* f_b2  = (const float*)d_in[21];
    const float* ln1g  = (const float*)d_in[22];
    const float* ln1b  = (const float*)d_in[23];
    const float* ln2g  = (const float*)d_in[24];
    const float* ln2b  = (const float*)d_in[25];
    const float* ln3g  = (const float*)d_in[26];
    const float* ln3b  = (const float*)d_in[27];
    float* out = (float*)d_out;

    float *x0, *xq, *qk, *vb, *attn, *tmp, *x1, *x2, *offaw, *ms, *wcat, *bcat;
    cudaGetSymbolAddress((void**)&x0,    g_x0);
    cudaGetSymbolAddress((void**)&xq,    g_xq);
    cudaGetSymbolAddress((void**)&qk,    g_qk);
    cudaGetSymbolAddress((void**)&vb,    g_v);
    cudaGetSymbolAddress((void**)&attn,  g_attn);
    cudaGetSymbolAddress((void**)&tmp,   g_tmp);
    cudaGetSymbolAddress((void**)&x1,    g_x1);
    cudaGetSymbolAddress((void**)&x2,    g_x2);
    cudaGetSymbolAddress((void**)&offaw, g_offaw);
    cudaGetSymbolAddress((void**)&ms,    g_ms);
    cudaGetSymbolAddress((void**)&wcat,  g_wcat);
    cudaGetSymbolAddress((void**)&bcat,  g_bcat);

    // 1) prep
    prep_kernel<<<(kPrepE + 255) / 256, 256>>>(query, qpos, vp_w,
                                               so_w, aw_w, so_b, aw_b);

    // 2) merged Q|K projection (N=512) and V projection
    mma_gemm<<<dim3(8, 63), 128>>>(xq, in_w,             in_b,       qk, kM, 512, kC, 0);
    mma_gemm<<<dim3(4, 63), 128>>>(x0, in_w + 512 * 256, in_b + 512, vb, kM, kC,  kC, 0);

    // 3) tensor-core flash attention
    flash_mma_kernel<<<dim3(8, kBS * kNH), 256>>>(qk, vb, attn);

    // 4) out-proj + residual + LN1 (fused: xq = x1 + qpos)
    mma_gemm<<<dim3(4, 63), 128>>>(attn, mha_ow, mha_ob, tmp, kM, kC, kC, 0);
    ln_kernel<<<kM, 256>>>(x0, tmp, ln1g, ln1b, x1, 0, qpos, xq);

    // 5) merged offset+weight projection (N=96)
    mma_gemm<<<dim3(2, 63), 128>>>(xq, wcat, bcat, offaw, kM, 96, kC, 0);

    // 6) fused raw-value sampling + per-head projection (+inline softmax)
    msfused_kernel<<<kM, 256>>>(value, refp, vp_b);

    // 7) msdeform out-proj + residual + LN2
    mma_gemm<<<dim3(4, 63), 128>>>(ms, op_w, op_b, tmp, kM, kC, kC, 0);
    ln_kernel<<<kM, 256>>>(x1, tmp, ln2g, ln2b, x2, 0, nullptr, nullptr);

    // 8) FFN + residual + LN3 (LN3 writes transposed into d_out)
    mma_gemm<<<dim3(8, 63), 128>>>(x2,  f_w1, f_b1, tmp, kM, kFFN, kC,   1);
    mma_gemm<<<dim3(4, 63), 128>>>(tmp, f_w2, f_b2, x0,  kM, kC,   kFFN, 0);
    ln_kernel<<<kM, 256>>>(x2, x0, ln3g, ln3b, out, 1, nullptr, nullptr);
}